// round 16
// baseline (speedup 1.0000x reference)
#include <cuda_runtime.h>
#include <cuda_bf16.h>
#include <cstdint>

#define T_DIM    2048
#define NUM_SEG  64
#define SEG      32
#define F_DIM    32
#define H_DIM    128
#define FEAT_DIM 4

#define RPB      8                       // rows per block (1 per warp)
#define ATHREADS 256                     // 8 warps
#define AGRID    (T_DIM / RPB)           // 256 blocks

// Dynamic smem layout (bytes):
//   fs   : [RPB][SEG][8] float4 = 32768  (offset 0)
//   h4_s : [SEG][32]     float4 = 16384  (offset 32768)
//   Wh4_s: [SEG][8]      float4 =  4096  (offset 49152)
//   Wq_s : [F_DIM][33]   float4 = 16896  (offset 53248)  pitch-33 conflict-free
//   mbar : u64                           (offset 70144)
#define OFF_H    32768
#define OFF_WH   49152
#define OFF_W    53248
#define OFF_MBAR 70144
#define SMEM_TOTAL 70160

__device__ __forceinline__ uint32_t smem_u32(const void* p) {
    uint32_t a;
    asm("{ .reg .u64 t; cvta.to.shared.u64 t, %1; cvt.u32.u64 %0, t; }" : "=r"(a) : "l"(p));
    return a;
}

__device__ __forceinline__ void bulk_g2s(uint32_t dst, const void* src, uint32_t bytes, uint32_t mbar) {
    asm volatile(
        "cp.async.bulk.shared::cta.global.mbarrier::complete_tx::bytes [%0], [%1], %2, [%3];"
        :: "r"(dst), "l"(src), "r"(bytes), "r"(mbar) : "memory");
}

__device__ __forceinline__ void mbar_wait0(uint32_t mbar) {
    uint32_t done = 0;
    while (!done) {
        asm volatile(
            "{\n\t.reg .pred p;\n\t"
            "mbarrier.try_wait.parity.acquire.cta.shared::cta.b64 p, [%1], 0, 0x989680;\n\t"
            "selp.b32 %0, 1, 0, p;\n\t}"
            : "=r"(done) : "r"(mbar) : "memory");
    }
}

// ---------------------------------------------------------------------------
// Single fused kernel: 256 blocks x 256 threads; 8 rows/block (1 per warp).
// Wh for the segment is computed DURING the TMA wait window (overlapped).
// ---------------------------------------------------------------------------
__global__ __launch_bounds__(ATHREADS, 1)
void horizon_fused_kernel(const float* __restrict__ f,
                          const float* __restrict__ h,
                          const float* __restrict__ features,
                          const float* __restrict__ hor,
                          const float* __restrict__ W_w,
                          const float* __restrict__ W_b,
                          float* __restrict__ S)
{
    extern __shared__ char smem[];
    float4* fs    = reinterpret_cast<float4*>(smem);             // [RPB][SEG][8]
    float4* h4_s  = reinterpret_cast<float4*>(smem + OFF_H);     // [SEG][32]
    float4* Wh4_s = reinterpret_cast<float4*>(smem + OFF_WH);    // [SEG][8]
    float4* Wq_s  = reinterpret_cast<float4*>(smem + OFF_W);     // [F_DIM][33]

    const int tid  = threadIdx.x;
    const int blk  = blockIdx.x;
    const int seg0 = (blk >> 2) * SEG;      // 4 blocks per segment

    const int warp = tid >> 5;              // 0..7
    const int lane = tid & 31;

    const int i  = blk * RPB + warp;        // global output row
    const int gj = seg0 + lane;             // lane's segment column

    // ---- mbarrier init + TMA issue (f + h only) ----
    const uint32_t mb = smem_u32(smem + OFF_MBAR);
    if (tid == 0) {
        asm volatile("mbarrier.init.shared.b64 [%0], 1;" :: "r"(mb) : "memory");
    }
    __syncthreads();
    if (tid == 0) {
        const uint32_t total = RPB * 4096 + 16384;     // 49152 B
        asm volatile("mbarrier.arrive.expect_tx.shared.b64 _, [%0], %1;"
                     :: "r"(mb), "r"(total) : "memory");
        #pragma unroll
        for (int r = 0; r < RPB; r++)
            bulk_g2s(smem_u32(fs + (size_t)r * SEG * 8),
                     f + ((size_t)(blk * RPB + r) * T_DIM + seg0) * F_DIM,
                     4096, mb);
        bulk_g2s(smem_u32(h4_s), h + (size_t)seg0 * H_DIM, 16384, mb);
    }

    // ---- Overlap part 1: mask loads + W staging (independent of TMA) ----
    const size_t mbi = (size_t)i * T_DIM + gj;
    const float bearing = hor[mbi];
    const float dist    = features[mbi * FEAT_DIM];
    const float badf = ((bearing < 0.f) || (dist > 10.f) || (i == gj)) ? 1.f : 0.f;

    {
        const float4* w4 = reinterpret_cast<const float4*>(W_w);
        #pragma unroll
        for (int n = tid; n < F_DIM * (H_DIM / 4); n += ATHREADS)   // 4 iters
            Wq_s[(n >> 5) * 33 + (n & 31)] = w4[n];
    }
    __syncthreads();   // W staged

    // ---- Overlap part 2: Wh for the whole segment (during TMA flight) ----
    // Warp computes rows j in {warp, warp+8, warp+16, warp+24}; lane = col ff.
    // W via conflict-free LDS.128; h rows via broadcast __ldg (L1-resident).
    {
        const float bias = W_b[lane];
        float acc0 = bias, acc1 = bias, acc2 = bias, acc3 = bias;
        const float4* hg = reinterpret_cast<const float4*>(h + (size_t)seg0 * H_DIM);
        #pragma unroll 8
        for (int k4 = 0; k4 < H_DIM / 4; k4++) {
            const float4 w  = Wq_s[lane * 33 + k4];
            const float4 a0 = __ldg(hg + (warp)      * 32 + k4);   // broadcast
            const float4 a1 = __ldg(hg + (warp + 8)  * 32 + k4);
            const float4 a2 = __ldg(hg + (warp + 16) * 32 + k4);
            const float4 a3 = __ldg(hg + (warp + 24) * 32 + k4);
            acc0 += a0.x * w.x + a0.y * w.y + a0.z * w.z + a0.w * w.w;
            acc1 += a1.x * w.x + a1.y * w.y + a1.z * w.z + a1.w * w.w;
            acc2 += a2.x * w.x + a2.y * w.y + a2.z * w.z + a2.w * w.w;
            acc3 += a3.x * w.x + a3.y * w.y + a3.z * w.z + a3.w * w.w;
        }
        float* WhF = reinterpret_cast<float*>(Wh4_s);
        WhF[(warp)      * 32 + lane] = acc0;   // bank = lane: conflict-free
        WhF[(warp + 8)  * 32 + lane] = acc1;
        WhF[(warp + 16) * 32 + lane] = acc2;
        WhF[(warp + 24) * 32 + lane] = acc3;
    }
    __syncthreads();   // Wh ready

    // ---- Wait for TMA data ----
    mbar_wait0(mb);

    // ---- Partial logit dots: lane l -> chunk c=l&7 of row j=4m+(l>>3) ----
    const int g = lane >> 3;
    const int c = lane & 7;
    const float4* fw = fs + (size_t)warp * SEG * 8;
    float val[8];
    #pragma unroll
    for (int m = 0; m < 8; m++) {
        const int j = 4 * m + g;
        const float4 a = fw[j * 8 + c];     // 128B contiguous per 8-lane phase
        const float4 w = Wh4_s[j * 8 + c];  // 128B contiguous per 8-lane phase
        float p = a.x * w.x + a.y * w.y + a.z * w.z + a.w * w.w;
        p += __shfl_xor_sync(0xFFFFFFFFu, p, 1);
        p += __shfl_xor_sync(0xFFFFFFFFu, p, 2);
        p += __shfl_xor_sync(0xFFFFFFFFu, p, 4);
        const float bm = __shfl_sync(0xFFFFFFFFu, badf, j);
        val[m] = (bm != 0.f) ? -1000.f : p;
    }

    // ---- Softmax over 32 columns (each replicated on 8 lanes) ----
    float mx = val[0];
    #pragma unroll
    for (int m = 1; m < 8; m++) mx = fmaxf(mx, val[m]);
    #pragma unroll
    for (int off = 16; off; off >>= 1)
        mx = fmaxf(mx, __shfl_xor_sync(0xFFFFFFFFu, mx, off));

    float e[8];
    float ls = 0.f;
    #pragma unroll
    for (int m = 0; m < 8; m++) { e[m] = expf(val[m] - mx); ls += e[m]; }
    #pragma unroll
    for (int off = 16; off; off >>= 1)
        ls += __shfl_xor_sync(0xFFFFFFFFu, ls, off);
    const float inv = 8.f / ls;             // ls = 8 * true_sum
    #pragma unroll
    for (int m = 0; m < 8; m++) e[m] *= inv;   // e[m] = attn[4m+g]

    // ---- S[i,:] = sum_j attn_j * h_seg[j,:]; lane owns 4 contiguous cols ----
    float4 Acc = make_float4(0.f, 0.f, 0.f, 0.f);
    #pragma unroll
    for (int jj = 0; jj < SEG; jj++) {
        const float a = __shfl_sync(0xFFFFFFFFu, e[jj >> 2], (jj & 3) * 8);
        const float4 hv = h4_s[jj * 32 + lane];   // conflict-free LDS.128
        Acc.x += a * hv.x;  Acc.y += a * hv.y;
        Acc.z += a * hv.z;  Acc.w += a * hv.w;
    }
    reinterpret_cast<float4*>(S + (size_t)i * H_DIM)[lane] = Acc;   // STG.128
}

extern "C" void kernel_launch(void* const* d_in, const int* in_sizes, int n_in,
                              void* d_out, int out_size)
{
    // metadata order: f, h, features, hor_bearings_MTX, W_w, W_b, sub_batches
    const float* f        = (const float*)d_in[0];
    const float* h        = (const float*)d_in[1];
    const float* features = (const float*)d_in[2];
    const float* hor      = (const float*)d_in[3];
    const float* W_w      = (const float*)d_in[4];
    const float* W_b      = (const float*)d_in[5];
    float* S = (float*)d_out;

    cudaFuncSetAttribute(horizon_fused_kernel,
                         cudaFuncAttributeMaxDynamicSharedMemorySize, SMEM_TOTAL);

    horizon_fused_kernel<<<AGRID, ATHREADS, SMEM_TOTAL>>>(
        f, h, features, hor, W_w, W_b, S);
}